// round 1
// baseline (speedup 1.0000x reference)
#include <cuda_runtime.h>

#define NQ      32768      // B*N queries
#define M_ANCH  8192
#define NPAIR   4096       // anchor pairs
#define DIM     8
#define QPT     4          // queries per thread
#define SEG     8          // anchor segments (split-M)
#define PAIRS_PER_SEG  (NPAIR / SEG)        // 512
#define GROUPS_PER_SEG (PAIRS_PER_SEG / 4)  // 128 (group = 4 pairs = 8 anchors)
#define QGRP    (NQ / QPT) // 8192

// pair layout (20 floats = 80B, 16B aligned):
//  [0..15]  : (a[2p][d], a[2p+1][d]) for d=0..7, interleaved
//  [16,17]  : (||a[2p]||^2, ||a[2p+1]||^2)
//  [18,19]  : pad
__device__ __align__(16) float g_packed[NPAIR * 20];
__device__ float g_pmin[NQ * SEG];
__device__ int   g_pidx[NQ * SEG];

typedef unsigned long long u64;

__device__ __forceinline__ u64 pk2(float a, float b) {
    u64 r; asm("mov.b64 %0,{%1,%2};" : "=l"(r) : "f"(a), "f"(b)); return r;
}
__device__ __forceinline__ u64 bcast2(float a) {
    u64 r; asm("mov.b64 %0,{%1,%1};" : "=l"(r) : "f"(a)); return r;
}
__device__ __forceinline__ void unpk2(u64 v, float& lo, float& hi) {
    asm("mov.b64 {%0,%1},%2;" : "=f"(lo), "=f"(hi) : "l"(v));
}
// packed fp32x2 FMA (sm_100+): d = a*b + c componentwise
__device__ __forceinline__ u64 ffma2(u64 a, u64 b, u64 c) {
    u64 d; asm("fma.rn.f32x2 %0,%1,%2,%3;" : "=l"(d) : "l"(a), "l"(b), "l"(c)); return d;
}

// ---------------------------------------------------------------------------
// 1) Repack anchors pairwise + fold squared norms
// ---------------------------------------------------------------------------
__global__ void prep_kernel(const float* __restrict__ anchors) {
    int p = blockIdx.x * blockDim.x + threadIdx.x;
    if (p >= NPAIR) return;
    const float* a0 = anchors + (2 * p) * DIM;
    float* o = g_packed + p * 20;
    float c0 = 0.f, c1 = 0.f;
#pragma unroll
    for (int d = 0; d < DIM; ++d) {
        float v0 = a0[d], v1 = a0[DIM + d];
        o[2 * d] = v0; o[2 * d + 1] = v1;
        c0 = fmaf(v0, v0, c0); c1 = fmaf(v1, v1, c1);
    }
    o[16] = c0; o[17] = c1; o[18] = 0.f; o[19] = 0.f;
}

// ---------------------------------------------------------------------------
// 2) Main argmin: each thread = 4 queries x 1 anchor segment (1024 anchors)
//    score = ||a||^2 - 2 x.a  via packed f32x2 FMAs over anchor pairs.
//    Track (group_min, group_id); recover exact index by recomputing the
//    winning group (bitwise-identical op order -> exact first-index match).
// ---------------------------------------------------------------------------
__global__ void __launch_bounds__(32, 14) argmin_kernel(const float* __restrict__ x) {
    int tid = blockIdx.x * 32 + threadIdx.x;   // 0 .. 65535
    int qg  = tid % QGRP;                      // query group (lanes -> consecutive)
    int seg = tid / QGRP;                      // anchor segment (warp-uniform)

    // Load 4 queries, premultiply by -2, broadcast into both f32x2 lanes
    u64 xq[QPT][DIM];
#pragma unroll
    for (int k = 0; k < QPT; ++k) {
        int q = qg + k * QGRP;
        const float4* xp = (const float4*)(x + q * DIM);
        float4 v0 = xp[0], v1 = xp[1];
        xq[k][0] = bcast2(-2.f * v0.x); xq[k][1] = bcast2(-2.f * v0.y);
        xq[k][2] = bcast2(-2.f * v0.z); xq[k][3] = bcast2(-2.f * v0.w);
        xq[k][4] = bcast2(-2.f * v1.x); xq[k][5] = bcast2(-2.f * v1.y);
        xq[k][6] = bcast2(-2.f * v1.z); xq[k][7] = bcast2(-2.f * v1.w);
    }

    float best[QPT]; int bestg[QPT];
#pragma unroll
    for (int k = 0; k < QPT; ++k) { best[k] = __int_as_float(0x7f800000); bestg[k] = 0; }

    const int pbase = seg * PAIRS_PER_SEG;
    const float4* pkd = (const float4*)(g_packed) + (size_t)pbase * 5; // 5 float4 per pair

    for (int g = 0; g < GROUPS_PER_SEG; ++g) {
        float gm[QPT];
#pragma unroll
        for (int j = 0; j < 4; ++j) {
            const float4* pb = pkd + (g * 4 + j) * 5;
            float4 u0 = pb[0], u1 = pb[1], u2 = pb[2], u3 = pb[3], u4 = pb[4];
            u64 a0 = pk2(u0.x, u0.y), a1 = pk2(u0.z, u0.w);
            u64 a2 = pk2(u1.x, u1.y), a3 = pk2(u1.z, u1.w);
            u64 a4 = pk2(u2.x, u2.y), a5 = pk2(u2.z, u2.w);
            u64 a6 = pk2(u3.x, u3.y), a7 = pk2(u3.z, u3.w);
            u64 cp = pk2(u4.x, u4.y);
#pragma unroll
            for (int k = 0; k < QPT; ++k) {
                u64 s = ffma2(xq[k][0], a0, cp);
                s = ffma2(xq[k][1], a1, s);
                s = ffma2(xq[k][2], a2, s);
                s = ffma2(xq[k][3], a3, s);
                s = ffma2(xq[k][4], a4, s);
                s = ffma2(xq[k][5], a5, s);
                s = ffma2(xq[k][6], a6, s);
                s = ffma2(xq[k][7], a7, s);
                float lo, hi; unpk2(s, lo, hi);
                float m = fminf(lo, hi);
                gm[k] = (j == 0) ? m : fminf(gm[k], m);
            }
        }
#pragma unroll
        for (int k = 0; k < QPT; ++k) {
            if (gm[k] < best[k]) { best[k] = gm[k]; bestg[k] = g; }  // strict < => earliest group
        }
    }

    // Recompute winning group per query; identical op order -> exact equality
#pragma unroll
    for (int k = 0; k < QPT; ++k) {
        int g = bestg[k];
        float sc[8];
#pragma unroll
        for (int j = 0; j < 4; ++j) {
            const float4* pb = pkd + (g * 4 + j) * 5;
            float4 u0 = pb[0], u1 = pb[1], u2 = pb[2], u3 = pb[3], u4 = pb[4];
            u64 s = ffma2(xq[k][0], pk2(u0.x, u0.y), pk2(u4.x, u4.y));
            s = ffma2(xq[k][1], pk2(u0.z, u0.w), s);
            s = ffma2(xq[k][2], pk2(u1.x, u1.y), s);
            s = ffma2(xq[k][3], pk2(u1.z, u1.w), s);
            s = ffma2(xq[k][4], pk2(u2.x, u2.y), s);
            s = ffma2(xq[k][5], pk2(u2.z, u2.w), s);
            s = ffma2(xq[k][6], pk2(u3.x, u3.y), s);
            s = ffma2(xq[k][7], pk2(u3.z, u3.w), s);
            unpk2(s, sc[2 * j], sc[2 * j + 1]);
        }
        int loc = 0;
#pragma unroll
        for (int j = 7; j >= 0; --j)
            if (sc[j] == best[k]) loc = j;   // first (lowest) index match
        int aidx = (pbase + g * 4) * 2 + loc;
        int q = qg + k * QGRP;
        g_pmin[q * SEG + seg] = best[k];
        g_pidx[q * SEG + seg] = aidx;
    }
}

// ---------------------------------------------------------------------------
// 3) Reduce segments + final q_sample: out = sa*x + sb*anchors[idx]
// ---------------------------------------------------------------------------
__global__ void reduce_kernel(const float* __restrict__ x,
                              const float* __restrict__ anchors,
                              const float* __restrict__ sac,
                              const float* __restrict__ somc,
                              const int*   __restrict__ t,
                              float* __restrict__ out) {
    int q = blockIdx.x * blockDim.x + threadIdx.x;
    if (q >= NQ) return;
    float bm = __int_as_float(0x7f800000); int bi = 0;
#pragma unroll
    for (int s = 0; s < SEG; ++s) {                // ascending segments, strict <
        float m = g_pmin[q * SEG + s];
        int   i = g_pidx[q * SEG + s];
        if (m < bm) { bm = m; bi = i; }
    }
    int b  = q / 2048;                             // N = 2048
    int tt = t[b];
    float sa = sac[tt], sb = somc[tt];
    const float4* ap = (const float4*)(anchors + (size_t)bi * DIM);
    const float4* xp = (const float4*)(x + (size_t)q * DIM);
    float4 a0 = ap[0], a1 = ap[1], x0 = xp[0], x1 = xp[1];
    float4 o0, o1;
    o0.x = sa * x0.x + sb * a0.x; o0.y = sa * x0.y + sb * a0.y;
    o0.z = sa * x0.z + sb * a0.z; o0.w = sa * x0.w + sb * a0.w;
    o1.x = sa * x1.x + sb * a1.x; o1.y = sa * x1.y + sb * a1.y;
    o1.z = sa * x1.z + sb * a1.z; o1.w = sa * x1.w + sb * a1.w;
    float4* op = (float4*)(out + (size_t)q * DIM);
    op[0] = o0; op[1] = o1;
}

// ---------------------------------------------------------------------------
extern "C" void kernel_launch(void* const* d_in, const int* in_sizes, int n_in,
                              void* d_out, int out_size) {
    const float* x    = nullptr;
    const float* anch = nullptr;
    const float* sac  = nullptr;
    const float* somc = nullptr;
    const int*   t    = nullptr;
    for (int i = 0; i < n_in; ++i) {
        int s = in_sizes[i];
        if (s == NQ * DIM && !x)          x    = (const float*)d_in[i];
        else if (s == M_ANCH * DIM)       anch = (const float*)d_in[i];
        else if (s == 1000) { if (!sac) sac = (const float*)d_in[i];
                              else      somc = (const float*)d_in[i]; }
        else if (s == 16)                 t    = (const int*)d_in[i];
    }
    prep_kernel<<<(NPAIR + 255) / 256, 256>>>(anch);
    argmin_kernel<<<(NQ / QPT) * SEG / 32, 32>>>(x);
    reduce_kernel<<<(NQ + 255) / 256, 256>>>(x, anch, sac, somc, t, (float*)d_out);
}

// round 2
// speedup vs baseline: 1.1659x; 1.1659x over previous
#include <cuda_runtime.h>

#define NQ   32768      // B*N queries
#define MA   8192       // anchors
#define DIM  8
#define SEG  4          // anchor segments
#define APS  (MA/SEG)   // 2048 anchors per segment
#define CHUNK 256       // anchors staged in smem at a time
#define NCHUNK (APS/CHUNK)   // 8
#define QPB  128        // queries per block (4 warps x 32)

// prep outputs: tf32 hi/lo split planes + exact fp32 norms
__device__ __align__(16) float g_plane0[MA*8];  // [anchor][k0..3][hi,lo]
__device__ __align__(16) float g_plane1[MA*8];  // [anchor][k4..7][hi,lo]
__device__ __align__(16) float g_norm[MA];
__device__ float g_pmin[NQ*SEG];
__device__ int   g_pidx[NQ*SEG];

__device__ __forceinline__ unsigned f2tf(float v) {
    unsigned r; asm("cvt.rna.tf32.f32 %0,%1;" : "=r"(r) : "f"(v)); return r;
}

// mma.sync m16n8k8 tf32, fp32 accum, explicit C
__device__ __forceinline__ void mma8c(float d[4], const unsigned a[4],
                                      unsigned b0, unsigned b1,
                                      float c0, float c1, float c2, float c3) {
    asm("mma.sync.aligned.m16n8k8.row.col.f32.tf32.tf32.f32 "
        "{%0,%1,%2,%3},{%4,%5,%6,%7},{%8,%9},{%10,%11,%12,%13};"
        : "=f"(d[0]), "=f"(d[1]), "=f"(d[2]), "=f"(d[3])
        : "r"(a[0]), "r"(a[1]), "r"(a[2]), "r"(a[3]),
          "r"(b0), "r"(b1),
          "f"(c0), "f"(c1), "f"(c2), "f"(c3));
}
__device__ __forceinline__ void mma8acc(float d[4], const unsigned a[4],
                                        unsigned b0, unsigned b1) {
    asm("mma.sync.aligned.m16n8k8.row.col.f32.tf32.tf32.f32 "
        "{%0,%1,%2,%3},{%4,%5,%6,%7},{%8,%9},{%10,%11,%12,%13};"
        : "=f"(d[0]), "=f"(d[1]), "=f"(d[2]), "=f"(d[3])
        : "r"(a[0]), "r"(a[1]), "r"(a[2]), "r"(a[3]),
          "r"(b0), "r"(b1),
          "f"(d[0]), "f"(d[1]), "f"(d[2]), "f"(d[3]));
}

// ---------------------------------------------------------------------------
// 1) Prep: split anchors into tf32 hi/lo planes, compute exact fp32 norms
// ---------------------------------------------------------------------------
__global__ void prep_kernel(const float* __restrict__ anchors) {
    int a = blockIdx.x * 256 + threadIdx.x;
    if (a >= MA) return;
    const float4* ap = (const float4*)(anchors + a * DIM);
    float4 v0 = ap[0], v1 = ap[1];
    float v[8] = {v0.x, v0.y, v0.z, v0.w, v1.x, v1.y, v1.z, v1.w};
    float nrm = 0.f;
#pragma unroll
    for (int d = 0; d < 8; ++d) nrm = fmaf(v[d], v[d], nrm);
    g_norm[a] = nrm;
#pragma unroll
    for (int k = 0; k < 4; ++k) {
        unsigned hi = f2tf(v[k]);
        float lo = v[k] - __uint_as_float(hi);
        g_plane0[a * 8 + k * 2]     = __uint_as_float(hi);
        g_plane0[a * 8 + k * 2 + 1] = __uint_as_float(f2tf(lo));
    }
#pragma unroll
    for (int k = 4; k < 8; ++k) {
        unsigned hi = f2tf(v[k]);
        float lo = v[k] - __uint_as_float(hi);
        g_plane1[a * 8 + (k - 4) * 2]     = __uint_as_float(hi);
        g_plane1[a * 8 + (k - 4) * 2 + 1] = __uint_as_float(f2tf(lo));
    }
}

// ---------------------------------------------------------------------------
// 2) Main: tensor-core argmin. Block = 4 warps x 32 queries x 1 segment.
//    Scores S = -2 x.a + ||a||^2 via 3xTF32 mma (hi*hi + hi*lo + lo*hi),
//    norms folded via C operand. Track per-thread min over 32-anchor blocks,
//    exact fp32 rescore of the winning block at the end.
// ---------------------------------------------------------------------------
__global__ void __launch_bounds__(128, 4)
argmin_mma(const float* __restrict__ x, const float* __restrict__ anchors) {
    __shared__ float sp0[CHUNK * 8];
    __shared__ float sp1[CHUNK * 8];
    __shared__ float snrm[CHUNK];

    int seg  = blockIdx.x & (SEG - 1);
    int qblk = blockIdx.x >> 2;
    int warp = threadIdx.x >> 5, lane = threadIdx.x & 31;
    int gid = lane >> 2, tig = lane & 3;
    int qb = qblk * QPB + warp * 32;
    int abase_seg = seg * APS;

    // A fragments: 2 M-tiles (rows qb..qb+15, qb+16..qb+31), hi/lo tf32,
    // queries premultiplied by -2.
    unsigned ah[2][4], al[2][4];
#pragma unroll
    for (int mt = 0; mt < 2; ++mt) {
        int r = qb + mt * 16 + gid;
#pragma unroll
        for (int i = 0; i < 4; ++i) {
            int row = r + (i & 1) * 8;
            int k = tig + (i >> 1) * 4;
            float v = -2.0f * __ldg(x + row * 8 + k);
            unsigned hi = f2tf(v);
            float lo = v - __uint_as_float(hi);
            ah[mt][i] = hi;
            al[mt][i] = f2tf(lo);
        }
    }

    float best[4]; int bblk[4];
#pragma unroll
    for (int s = 0; s < 4; ++s) { best[s] = __int_as_float(0x7f800000); bblk[s] = 0; }

    for (int c = 0; c < NCHUNK; ++c) {
        __syncthreads();
        {   // stage chunk into smem (prepacked layout, straight copy)
            int ab = abase_seg + c * CHUNK;
            const float4* s0 = (const float4*)(g_plane0 + ab * 8);
            const float4* s1 = (const float4*)(g_plane1 + ab * 8);
            float4* d0 = (float4*)sp0; float4* d1 = (float4*)sp1;
            for (int i = threadIdx.x; i < CHUNK * 2; i += 128) { d0[i] = s0[i]; d1[i] = s1[i]; }
            if (threadIdx.x < CHUNK / 4) {
                ((float4*)snrm)[threadIdx.x] = ((const float4*)(g_norm + ab))[threadIdx.x];
            }
        }
        __syncthreads();

        for (int blk = 0; blk < 8; ++blk) {      // 32-anchor blocks
            float m[4];
#pragma unroll
            for (int j = 0; j < 4; ++j) {        // 8-anchor mma groups
                int grp = blk * 4 + j;
                int n0 = grp * 8 + gid;
                float2 b0 = *(const float2*)(sp0 + n0 * 8 + tig * 2);
                float2 b1 = *(const float2*)(sp1 + n0 * 8 + tig * 2);
                float2 cn = *(const float2*)(snrm + grp * 8 + tig * 2);
                unsigned bh0 = __float_as_uint(b0.x), bl0 = __float_as_uint(b0.y);
                unsigned bh1 = __float_as_uint(b1.x), bl1 = __float_as_uint(b1.y);
#pragma unroll
                for (int mt = 0; mt < 2; ++mt) {
                    float d[4];
                    mma8c (d, ah[mt], bh0, bh1, cn.x, cn.y, cn.x, cn.y); // hi*hi + norms
                    mma8acc(d, ah[mt], bl0, bl1);                        // + hi*lo
                    mma8acc(d, al[mt], bh0, bh1);                        // + lo*hi
                    float p0 = fminf(d[0], d[1]);   // query row r
                    float p1 = fminf(d[2], d[3]);   // query row r+8
                    if (j == 0) { m[mt * 2] = p0; m[mt * 2 + 1] = p1; }
                    else { m[mt * 2] = fminf(m[mt * 2], p0); m[mt * 2 + 1] = fminf(m[mt * 2 + 1], p1); }
                }
            }
            int blkg = c * 8 + blk;
#pragma unroll
            for (int s = 0; s < 4; ++s)
                if (m[s] < best[s]) { best[s] = m[s]; bblk[s] = blkg; }
        }
    }

    // Recovery: per slot, pick winning 32-anchor block across the 4 lanes of
    // the quad, then rescore those 32 anchors exactly in fp32 (4 lanes x 8).
#pragma unroll
    for (int s = 0; s < 4; ++s) {
        int mt = s >> 1, half = s & 1;
        float bv = best[s]; int bb = bblk[s];
#pragma unroll
        for (int off = 1; off <= 2; off <<= 1) {
            float ov = __shfl_xor_sync(0xffffffffu, bv, off);
            int   ob = __shfl_xor_sync(0xffffffffu, bb, off);
            if (ov < bv || (ov == bv && ob < bb)) { bv = ov; bb = ob; }
        }
        int q = qb + mt * 16 + gid + half * 8;
        const float4* xp = (const float4*)(x + (size_t)q * 8);
        float4 x0 = xp[0], x1 = xp[1];
        int a0i = abase_seg + bb * 32 + tig * 8;
        float ev = __int_as_float(0x7f800000); int ei = 0;
#pragma unroll
        for (int j = 0; j < 8; ++j) {
            int a = a0i + j;
            const float4* ap = (const float4*)(anchors + (size_t)a * 8);
            float4 a0 = ap[0], a1 = ap[1];
            float dot = x0.x * a0.x;
            dot = fmaf(x0.y, a0.y, dot);
            dot = fmaf(x0.z, a0.z, dot);
            dot = fmaf(x0.w, a0.w, dot);
            dot = fmaf(x1.x, a1.x, dot);
            dot = fmaf(x1.y, a1.y, dot);
            dot = fmaf(x1.z, a1.z, dot);
            dot = fmaf(x1.w, a1.w, dot);
            float sv = fmaf(-2.f, dot, g_norm[a]);
            if (sv < ev) { ev = sv; ei = a; }
        }
#pragma unroll
        for (int off = 1; off <= 2; off <<= 1) {
            float ov = __shfl_xor_sync(0xffffffffu, ev, off);
            int   oi = __shfl_xor_sync(0xffffffffu, ei, off);
            if (ov < ev || (ov == ev && oi < ei)) { ev = ov; ei = oi; }
        }
        if (tig == 0) { g_pmin[q * SEG + seg] = ev; g_pidx[q * SEG + seg] = ei; }
    }
}

// ---------------------------------------------------------------------------
// 3) Reduce segments + q_sample epilogue
// ---------------------------------------------------------------------------
__global__ void reduce_kernel(const float* __restrict__ x,
                              const float* __restrict__ anchors,
                              const float* __restrict__ sac,
                              const float* __restrict__ somc,
                              const int*   __restrict__ t,
                              float* __restrict__ out) {
    int q = blockIdx.x * blockDim.x + threadIdx.x;
    if (q >= NQ) return;
    float bm = __int_as_float(0x7f800000); int bi = 0;
#pragma unroll
    for (int s = 0; s < SEG; ++s) {          // ascending segs, strict <
        float m = g_pmin[q * SEG + s];
        int   i = g_pidx[q * SEG + s];
        if (m < bm || (m == bm && i < bi)) { bm = m; bi = i; }
    }
    int b = q / 2048;                        // N = 2048
    int tt = t[b];
    float sa = sac[tt], sb = somc[tt];
    const float4* ap = (const float4*)(anchors + (size_t)bi * DIM);
    const float4* xp = (const float4*)(x + (size_t)q * DIM);
    float4 a0 = ap[0], a1 = ap[1], x0 = xp[0], x1 = xp[1];
    float4 o0, o1;
    o0.x = sa * x0.x + sb * a0.x; o0.y = sa * x0.y + sb * a0.y;
    o0.z = sa * x0.z + sb * a0.z; o0.w = sa * x0.w + sb * a0.w;
    o1.x = sa * x1.x + sb * a1.x; o1.y = sa * x1.y + sb * a1.y;
    o1.z = sa * x1.z + sb * a1.z; o1.w = sa * x1.w + sb * a1.w;
    float4* op = (float4*)(out + (size_t)q * DIM);
    op[0] = o0; op[1] = o1;
}

// ---------------------------------------------------------------------------
extern "C" void kernel_launch(void* const* d_in, const int* in_sizes, int n_in,
                              void* d_out, int out_size) {
    const float* x    = nullptr;
    const float* anch = nullptr;
    const float* sac  = nullptr;
    const float* somc = nullptr;
    const int*   t    = nullptr;
    for (int i = 0; i < n_in; ++i) {
        int s = in_sizes[i];
        if (s == NQ * DIM && !x)          x    = (const float*)d_in[i];
        else if (s == MA * DIM)           anch = (const float*)d_in[i];
        else if (s == 1000) { if (!sac) sac = (const float*)d_in[i];
                              else      somc = (const float*)d_in[i]; }
        else if (s == 16)                 t    = (const int*)d_in[i];
    }
    prep_kernel<<<MA / 256, 256>>>(anch);
    argmin_mma<<<(NQ / QPB) * SEG, 128>>>(x, anch);
    reduce_kernel<<<(NQ + 255) / 256, 256>>>(x, anch, sac, somc, t, (float*)d_out);
}

// round 3
// speedup vs baseline: 1.4023x; 1.2027x over previous
#include <cuda_runtime.h>
#include <cuda_fp16.h>

#define NQ   32768
#define MA   8192
#define DIM  8
#define SEG  4
#define APS  (MA/SEG)        // 2048 anchors per segment
#define CHUNK 512
#define NCHUNK (APS/CHUNK)   // 4
#define FLT_INF __int_as_float(0x7f800000)

// scratch (device globals: no allocation allowed)
__device__ float2   g_bs[SEG * NQ];    // (best, secondbest) coarse per (seg, query)
__device__ int      g_blk[SEG * NQ];   // best 32-anchor block id per (seg, query)
__device__ unsigned g_bmax[DIM];       // per-dim max |anchor coord| as float bits (monotonic)

// fp16 m16n8k16 MMA, fp32 accum; B reg duplicated (k8..15 repeat k0..7)
__device__ __forceinline__ void hmma(float d[4],
                                     unsigned a0, unsigned a1, unsigned a2, unsigned a3,
                                     unsigned b, float c0, float c1) {
    asm("mma.sync.aligned.m16n8k16.row.col.f32.f16.f16.f32 "
        "{%0,%1,%2,%3},{%4,%5,%6,%7},{%8,%9},{%10,%11,%12,%13};"
        : "=f"(d[0]), "=f"(d[1]), "=f"(d[2]), "=f"(d[3])
        : "r"(a0), "r"(a1), "r"(a2), "r"(a3), "r"(b), "r"(b),
          "f"(c0), "f"(c1), "f"(c0), "f"(c1));
}

// ---------------------------------------------------------------------------
// 0) per-dim max |anchor coord|  (idempotent atomics; +floats compare as ints)
// ---------------------------------------------------------------------------
__global__ void bmax_kernel(const float* __restrict__ anchors) {
    int a = blockIdx.x * 256 + threadIdx.x;
    const float4* ap = (const float4*)(anchors + (size_t)a * DIM);
    float4 v0 = ap[0], v1 = ap[1];
    unsigned m[8] = { __float_as_uint(fabsf(v0.x)), __float_as_uint(fabsf(v0.y)),
                      __float_as_uint(fabsf(v0.z)), __float_as_uint(fabsf(v0.w)),
                      __float_as_uint(fabsf(v1.x)), __float_as_uint(fabsf(v1.y)),
                      __float_as_uint(fabsf(v1.z)), __float_as_uint(fabsf(v1.w)) };
    __shared__ unsigned sm[8];
    if (threadIdx.x < 8) sm[threadIdx.x] = 0;
    __syncthreads();
#pragma unroll
    for (int d = 0; d < 8; ++d) m[d] = __reduce_max_sync(0xffffffffu, m[d]);
    if ((threadIdx.x & 31) == 0)
#pragma unroll
        for (int d = 0; d < 8; ++d) atomicMax(&sm[d], m[d]);
    __syncthreads();
    if (threadIdx.x < 8) atomicMax(&g_bmax[threadIdx.x], sm[threadIdx.x]);
}

// ---------------------------------------------------------------------------
// 1) Coarse pass: 1 fp16 MMA per 16q x 8a. Block = 4 warps x 32 queries x 1 seg.
// ---------------------------------------------------------------------------
__global__ void __launch_bounds__(128, 8)
coarse_kernel(const float* __restrict__ x, const float* __restrict__ anchors) {
    __shared__ uint4 sbh[CHUNK];     // 8 fp16 per anchor
    __shared__ float snrm[CHUNK];    // exact fp32 norms

    int seg  = blockIdx.x & (SEG - 1);
    int qblk = blockIdx.x >> 2;
    int warp = threadIdx.x >> 5, lane = threadIdx.x & 31;
    int gid = lane >> 2, tig = lane & 3;
    int qb = qblk * 128 + warp * 32;

    // A fragments: a = -2x split exactly into fp16 hi+lo (K-packed)
    unsigned afr[2][4];
#pragma unroll
    for (int mt = 0; mt < 2; ++mt)
#pragma unroll
        for (int rh = 0; rh < 2; ++rh) {
            int row = qb + mt * 16 + rh * 8 + gid;
            float2 xv = *(const float2*)(x + row * 8 + tig * 2);
            float v0 = -2.f * xv.x, v1 = -2.f * xv.y;
            __half h0 = __float2half_rn(v0), h1 = __float2half_rn(v1);
            float l0 = v0 - __half2float(h0), l1 = v1 - __half2float(h1);
            __half2 hh = __halves2half2(h0, h1);
            __half2 ll = __floats2half2_rn(l0, l1);
            afr[mt][rh]     = *(unsigned*)&hh;
            afr[mt][2 + rh] = *(unsigned*)&ll;
        }

    float best[4], sec[4]; int blk[4];
#pragma unroll
    for (int s = 0; s < 4; ++s) { best[s] = FLT_INF; sec[s] = FLT_INF; blk[s] = 0; }

    for (int c = 0; c < NCHUNK; ++c) {
        __syncthreads();
        int cbase = seg * APS + c * CHUNK;
#pragma unroll
        for (int j = 0; j < CHUNK / 128; ++j) {       // stage + convert on the fly
            int al = threadIdx.x + j * 128;
            const float4* ap = (const float4*)(anchors + (size_t)(cbase + al) * DIM);
            float4 v0 = ap[0], v1 = ap[1];
            float nrm = v0.x * v0.x;
            nrm = fmaf(v0.y, v0.y, nrm); nrm = fmaf(v0.z, v0.z, nrm); nrm = fmaf(v0.w, v0.w, nrm);
            nrm = fmaf(v1.x, v1.x, nrm); nrm = fmaf(v1.y, v1.y, nrm); nrm = fmaf(v1.z, v1.z, nrm);
            nrm = fmaf(v1.w, v1.w, nrm);
            __half2 p0 = __floats2half2_rn(v0.x, v0.y);
            __half2 p1 = __floats2half2_rn(v0.z, v0.w);
            __half2 p2 = __floats2half2_rn(v1.x, v1.y);
            __half2 p3 = __floats2half2_rn(v1.z, v1.w);
            uint4 pk;
            pk.x = *(unsigned*)&p0; pk.y = *(unsigned*)&p1;
            pk.z = *(unsigned*)&p2; pk.w = *(unsigned*)&p3;
            sbh[al] = pk;
            snrm[al] = nrm;
        }
        __syncthreads();

#pragma unroll 1
        for (int tb = 0; tb < 16; ++tb) {             // 32-anchor tracking blocks
            float r[2][4];
#pragma unroll
            for (int j = 0; j < 4; ++j) {             // 8-anchor MMA groups
                int grp = tb * 4 + j;
                unsigned bb = ((const unsigned*)sbh)[(grp * 8 + gid) * 4 + tig];
                float2 cn = *(const float2*)(snrm + grp * 8 + tig * 2);
#pragma unroll
                for (int mt = 0; mt < 2; ++mt) {
                    float d[4];
                    hmma(d, afr[mt][0], afr[mt][1], afr[mt][2], afr[mt][3], bb, cn.x, cn.y);
                    if (j == 0) { r[mt][0] = d[0]; r[mt][1] = d[1]; r[mt][2] = d[2]; r[mt][3] = d[3]; }
                    else { r[mt][0] = fminf(r[mt][0], d[0]); r[mt][1] = fminf(r[mt][1], d[1]);
                           r[mt][2] = fminf(r[mt][2], d[2]); r[mt][3] = fminf(r[mt][3], d[3]); }
                }
            }
            int blkid = c * 16 + tb;
#pragma unroll
            for (int s = 0; s < 4; ++s) {
                int mt = s >> 1, rh = s & 1;
                float m = fminf(r[mt][rh * 2], r[mt][rh * 2 + 1]);
                if (m < best[s]) { sec[s] = best[s]; best[s] = m; blk[s] = blkid; }
                else sec[s] = fminf(sec[s], m);
            }
        }
    }

    // reduce across the 4 tig lanes of each quad; keep (best, blk, secondbest)
#pragma unroll
    for (int s = 0; s < 4; ++s) {
        float b = best[s], sc = sec[s]; int bk = blk[s];
#pragma unroll
        for (int off = 1; off <= 2; off <<= 1) {
            float ob = __shfl_xor_sync(0xffffffffu, b, off);
            int obk  = __shfl_xor_sync(0xffffffffu, bk, off);
            float os = __shfl_xor_sync(0xffffffffu, sc, off);
            sc = fminf(sc, os);
            if (ob < b || (ob == b && obk < bk)) { sc = fminf(sc, b); b = ob; bk = obk; }
            else sc = fminf(sc, ob);
        }
        if (tig == 0) {
            int q = qb + (s >> 1) * 16 + (s & 1) * 8 + gid;
            g_bs[seg * NQ + q] = make_float2(b, sc);
            g_blk[seg * NQ + q] = bk;
        }
    }
}

// ---------------------------------------------------------------------------
// 2) Finalize: exact fp32 rescore of provably-complete candidate set + q_sample
//    One warp per query.
// ---------------------------------------------------------------------------
__device__ __forceinline__ void score_upd(const float* __restrict__ anchors, int a,
                                          float4 x0, float4 x1, float& ev, int& ei) {
    const float4* ap = (const float4*)(anchors + (size_t)a * DIM);
    float4 a0 = ap[0], a1 = ap[1];
    float nrm = a0.x * a0.x;
    nrm = fmaf(a0.y, a0.y, nrm); nrm = fmaf(a0.z, a0.z, nrm); nrm = fmaf(a0.w, a0.w, nrm);
    nrm = fmaf(a1.x, a1.x, nrm); nrm = fmaf(a1.y, a1.y, nrm); nrm = fmaf(a1.z, a1.z, nrm);
    nrm = fmaf(a1.w, a1.w, nrm);
    float dot = x0.x * a0.x;
    dot = fmaf(x0.y, a0.y, dot); dot = fmaf(x0.z, a0.z, dot); dot = fmaf(x0.w, a0.w, dot);
    dot = fmaf(x1.x, a1.x, dot); dot = fmaf(x1.y, a1.y, dot); dot = fmaf(x1.z, a1.z, dot);
    dot = fmaf(x1.w, a1.w, dot);
    float sv = fmaf(-2.f, dot, nrm);
    if (sv < ev || (sv == ev && a < ei)) { ev = sv; ei = a; }
}

__global__ void __launch_bounds__(256)
finalize_kernel(const float* __restrict__ x, const float* __restrict__ anchors,
                const float* __restrict__ sac, const float* __restrict__ somc,
                const int* __restrict__ t, float* __restrict__ out) {
    int q = blockIdx.x * 8 + (threadIdx.x >> 5);
    int lane = threadIdx.x & 31;

    float2 bs[SEG]; int bk[SEG];
    float m1 = FLT_INF;
#pragma unroll
    for (int s = 0; s < SEG; ++s) {
        bs[s] = g_bs[s * NQ + q];
        bk[s] = g_blk[s * NQ + q];
        m1 = fminf(m1, bs[s].x);
    }

    const float4* xp = (const float4*)(x + (size_t)q * DIM);
    float4 x0 = xp[0], x1 = xp[1];
    // rigorous coarse-error bound: E = 2^-11 * sum_d |2x_d| * bmax_d  (+ slack)
    float S = fabsf(x0.x) * __uint_as_float(g_bmax[0]);
    S = fmaf(fabsf(x0.y), __uint_as_float(g_bmax[1]), S);
    S = fmaf(fabsf(x0.z), __uint_as_float(g_bmax[2]), S);
    S = fmaf(fabsf(x0.w), __uint_as_float(g_bmax[3]), S);
    S = fmaf(fabsf(x1.x), __uint_as_float(g_bmax[4]), S);
    S = fmaf(fabsf(x1.y), __uint_as_float(g_bmax[5]), S);
    S = fmaf(fabsf(x1.z), __uint_as_float(g_bmax[6]), S);
    S = fmaf(fabsf(x1.w), __uint_as_float(g_bmax[7]), S);
    S *= 2.f;
    float thr = m1 + 1.24e-3f * S + 1e-4f * (1.f + S);   // m1 + 2E + slack

    bool fb = false;
#pragma unroll
    for (int s = 0; s < SEG; ++s) fb |= (bs[s].y <= thr);

    float ev = FLT_INF; int ei = 0x7fffffff;
    if (!fb) {
#pragma unroll
        for (int s = 0; s < SEG; ++s)
            if (bs[s].x <= thr)
                score_upd(anchors, s * APS + bk[s] * 32 + lane, x0, x1, ev, ei);
    } else {
        for (int it = 0; it < MA / 32; ++it)
            score_upd(anchors, it * 32 + lane, x0, x1, ev, ei);
    }
#pragma unroll
    for (int off = 16; off >= 1; off >>= 1) {
        float ov = __shfl_xor_sync(0xffffffffu, ev, off);
        int   oi = __shfl_xor_sync(0xffffffffu, ei, off);
        if (ov < ev || (ov == ev && oi < ei)) { ev = ov; ei = oi; }
    }

    if (lane == 0) {
        int tt = t[q >> 11];                              // N = 2048
        float sa = sac[tt], sb = somc[tt];
        const float4* ap = (const float4*)(anchors + (size_t)ei * DIM);
        float4 a0 = ap[0], a1 = ap[1];
        float4 o0, o1;
        o0.x = sa * x0.x + sb * a0.x; o0.y = sa * x0.y + sb * a0.y;
        o0.z = sa * x0.z + sb * a0.z; o0.w = sa * x0.w + sb * a0.w;
        o1.x = sa * x1.x + sb * a1.x; o1.y = sa * x1.y + sb * a1.y;
        o1.z = sa * x1.z + sb * a1.z; o1.w = sa * x1.w + sb * a1.w;
        float4* op = (float4*)(out + (size_t)q * DIM);
        op[0] = o0; op[1] = o1;
    }
}

// ---------------------------------------------------------------------------
extern "C" void kernel_launch(void* const* d_in, const int* in_sizes, int n_in,
                              void* d_out, int out_size) {
    const float* x    = nullptr;
    const float* anch = nullptr;
    const float* sac  = nullptr;
    const float* somc = nullptr;
    const int*   t    = nullptr;
    for (int i = 0; i < n_in; ++i) {
        int s = in_sizes[i];
        if (s == NQ * DIM && !x)          x    = (const float*)d_in[i];
        else if (s == MA * DIM)           anch = (const float*)d_in[i];
        else if (s == 1000) { if (!sac) sac = (const float*)d_in[i];
                              else      somc = (const float*)d_in[i]; }
        else if (s == 16)                 t    = (const int*)d_in[i];
    }
    bmax_kernel<<<MA / 256, 256>>>(anch);
    coarse_kernel<<<(NQ / 128) * SEG, 128>>>(x, anch);
    finalize_kernel<<<NQ / 8, 256>>>(x, anch, sac, somc, t, (float*)d_out);
}

// round 5
// speedup vs baseline: 1.6055x; 1.1449x over previous
#include <cuda_runtime.h>

#define NQ   32768
#define MA   8192
#define DIM  8
#define SEG  4
#define APS  (MA/SEG)        // 2048 anchors per segment
#define CHUNK 512
#define NCHUNK (APS/CHUNK)   // 4
#define BLKA  64             // tracking block = 64 anchors
#define NBLK  (APS/BLKA)     // 32 blocks per segment
#define FLT_INF __int_as_float(0x7f800000)

// scratch
__device__ float4   g_f4[SEG * NQ];     // (b1, b2, b3, __int_as_float(blk1))
__device__ int      g_blk2[SEG * NQ];
__device__ unsigned g_bmax[DIM];        // per-dim max |anchor| bits (monotonic)

__device__ __forceinline__ unsigned f2tf(float v) {
    unsigned r; asm("cvt.rna.tf32.f32 %0,%1;" : "=r"(r) : "f"(v)); return r;
}

// m16n8k8 tf32, fp32 accum, C folded (anchor norms)
__device__ __forceinline__ void mma8(float d[4], const unsigned a[4],
                                     unsigned b0, unsigned b1, float c0, float c1) {
    asm("mma.sync.aligned.m16n8k8.row.col.f32.tf32.tf32.f32 "
        "{%0,%1,%2,%3},{%4,%5,%6,%7},{%8,%9},{%10,%11,%12,%13};"
        : "=f"(d[0]), "=f"(d[1]), "=f"(d[2]), "=f"(d[3])
        : "r"(a[0]), "r"(a[1]), "r"(a[2]), "r"(a[3]),
          "r"(b0), "r"(b1), "f"(c0), "f"(c1), "f"(c0), "f"(c1));
}

// insert v into sorted triple (b1<=b2<=b3), ids for first two
__device__ __forceinline__ void ins3(float v, int id, float& b1, int& i1,
                                     float& b2, int& i2, float& b3) {
    if (v < b3) {
        if (v < b2) {
            b3 = b2;
            if (v < b1) { b2 = b1; i2 = i1; b1 = v; i1 = id; }
            else        { b2 = v; i2 = id; }
        } else b3 = v;
    }
}

// ---------------------------------------------------------------------------
// 1) Coarse: single-pass tf32 MMA. Block = 4 warps x 32 queries x 1 segment.
//    score = -2 x.a + ||a||^2 (norm via C). Track top-3 64-anchor block mins.
// ---------------------------------------------------------------------------
__global__ void __launch_bounds__(128, 7)
coarse_kernel(const float* __restrict__ x, const float* __restrict__ anchors) {
    __shared__ unsigned sb[CHUNK * 8];   // [anchor][(v_k, v_{k+4}) pairs, k=0..3] tf32
    __shared__ float snrm[CHUNK];

    int seg  = blockIdx.x & (SEG - 1);
    int qblk = blockIdx.x >> 2;
    int warp = threadIdx.x >> 5, lane = threadIdx.x & 31;
    int gid = lane >> 2, tig = lane & 3;
    int qb = qblk * 128 + warp * 32;
    int abase = seg * APS;

    // fold bmax computation into the 4 qblk==0 blocks (one per segment)
    if (qblk == 0) {
        unsigned um[8];
#pragma unroll
        for (int d = 0; d < 8; ++d) um[d] = 0;
        for (int al = threadIdx.x; al < APS; al += 128) {
            const float4* ap = (const float4*)(anchors + (size_t)(abase + al) * DIM);
            float4 v0 = ap[0], v1 = ap[1];
            um[0] = max(um[0], __float_as_uint(fabsf(v0.x)));
            um[1] = max(um[1], __float_as_uint(fabsf(v0.y)));
            um[2] = max(um[2], __float_as_uint(fabsf(v0.z)));
            um[3] = max(um[3], __float_as_uint(fabsf(v0.w)));
            um[4] = max(um[4], __float_as_uint(fabsf(v1.x)));
            um[5] = max(um[5], __float_as_uint(fabsf(v1.y)));
            um[6] = max(um[6], __float_as_uint(fabsf(v1.z)));
            um[7] = max(um[7], __float_as_uint(fabsf(v1.w)));
        }
#pragma unroll
        for (int d = 0; d < 8; ++d) {
            um[d] = __reduce_max_sync(0xffffffffu, um[d]);
            if (lane == 0) atomicMax(&g_bmax[d], um[d]);
        }
    }

    // A fragments (2 M-tiles x 16 rows), a = tf32(-2x)
    unsigned ah[2][4];
#pragma unroll
    for (int mt = 0; mt < 2; ++mt)
#pragma unroll
        for (int i = 0; i < 4; ++i) {
            int row = qb + mt * 16 + (i & 1) * 8 + gid;
            int k = tig + (i >> 1) * 4;
            ah[mt][i] = f2tf(-2.0f * __ldg(x + row * 8 + k));
        }

    float b1[4], b2[4], b3[4]; int i1[4], i2[4];
#pragma unroll
    for (int s = 0; s < 4; ++s) { b1[s] = FLT_INF; b2[s] = FLT_INF; b3[s] = FLT_INF; i1[s] = 0; i2[s] = 0; }

    for (int c = 0; c < NCHUNK; ++c) {
        __syncthreads();
        int cbase = abase + c * CHUNK;
#pragma unroll
        for (int jj = 0; jj < CHUNK / 128; ++jj) {
            int al = threadIdx.x + jj * 128;
            const float4* ap = (const float4*)(anchors + (size_t)(cbase + al) * DIM);
            float4 v0 = ap[0], v1 = ap[1];
            float nrm = v0.x * v0.x;
            nrm = fmaf(v0.y, v0.y, nrm); nrm = fmaf(v0.z, v0.z, nrm); nrm = fmaf(v0.w, v0.w, nrm);
            nrm = fmaf(v1.x, v1.x, nrm); nrm = fmaf(v1.y, v1.y, nrm); nrm = fmaf(v1.z, v1.z, nrm);
            nrm = fmaf(v1.w, v1.w, nrm);
            snrm[al] = nrm;
            unsigned* o = sb + al * 8;
            o[0] = f2tf(v0.x); o[1] = f2tf(v1.x);   // (k0, k4)
            o[2] = f2tf(v0.y); o[3] = f2tf(v1.y);   // (k1, k5)
            o[4] = f2tf(v0.z); o[5] = f2tf(v1.z);   // (k2, k6)
            o[6] = f2tf(v0.w); o[7] = f2tf(v1.w);   // (k3, k7)
        }
        __syncthreads();

#pragma unroll 1
        for (int tb = 0; tb < CHUNK / BLKA; ++tb) {     // 64-anchor blocks
            float r[2][4];
#pragma unroll
            for (int j = 0; j < 8; ++j) {               // 8-anchor MMA groups
                int grp = tb * 8 + j;
                const uint2 bv = *(const uint2*)(sb + (grp * 8 + gid) * 8 + tig * 2);
                const float2 cn = *(const float2*)(snrm + grp * 8 + tig * 2);
#pragma unroll
                for (int mt = 0; mt < 2; ++mt) {
                    float d[4];
                    mma8(d, ah[mt], bv.x, bv.y, cn.x, cn.y);
                    if (j == 0) { r[mt][0] = d[0]; r[mt][1] = d[1]; r[mt][2] = d[2]; r[mt][3] = d[3]; }
                    else { r[mt][0] = fminf(r[mt][0], d[0]); r[mt][1] = fminf(r[mt][1], d[1]);
                           r[mt][2] = fminf(r[mt][2], d[2]); r[mt][3] = fminf(r[mt][3], d[3]); }
                }
            }
            int blkid = c * (CHUNK / BLKA) + tb;
#pragma unroll
            for (int s = 0; s < 4; ++s) {
                int mt = s >> 1, rh = s & 1;
                float m = fminf(r[mt][rh * 2], r[mt][rh * 2 + 1]);
                ins3(m, blkid, b1[s], i1[s], b2[s], i2[s], b3[s]);
            }
        }
    }

    // quad (tig-lane) merge of top-3 lists; dup block-ids allowed (safe)
#pragma unroll
    for (int s = 0; s < 4; ++s) {
        float a1 = b1[s], a2 = b2[s], a3 = b3[s]; int j1 = i1[s], j2 = i2[s];
#pragma unroll
        for (int off = 1; off <= 2; off <<= 1) {
            float o1 = __shfl_xor_sync(0xffffffffu, a1, off);
            float o2 = __shfl_xor_sync(0xffffffffu, a2, off);
            float o3 = __shfl_xor_sync(0xffffffffu, a3, off);
            int oj1 = __shfl_xor_sync(0xffffffffu, j1, off);
            int oj2 = __shfl_xor_sync(0xffffffffu, j2, off);
            ins3(o1, oj1, a1, j1, a2, j2, a3);
            ins3(o2, oj2, a1, j1, a2, j2, a3);
            ins3(o3, 0,  a1, j1, a2, j2, a3);
        }
        if (tig == 0) {
            int q = qb + (s >> 1) * 16 + (s & 1) * 8 + gid;
            g_f4[seg * NQ + q] = make_float4(a1, a2, a3, __int_as_float(j1));
            g_blk2[seg * NQ + q] = j2;
        }
    }
}

// ---------------------------------------------------------------------------
// 2) Finalize: exact fp32 rescore of candidate blocks (provably complete),
//    rare full-scan fallback, then q_sample epilogue. One warp per query.
// ---------------------------------------------------------------------------
__device__ __forceinline__ void score_upd(const float* __restrict__ anchors, int a,
                                          float4 x0, float4 x1, float& ev, int& ei) {
    const float4* ap = (const float4*)(anchors + (size_t)a * DIM);
    float4 a0 = ap[0], a1 = ap[1];
    float nrm = a0.x * a0.x;
    nrm = fmaf(a0.y, a0.y, nrm); nrm = fmaf(a0.z, a0.z, nrm); nrm = fmaf(a0.w, a0.w, nrm);
    nrm = fmaf(a1.x, a1.x, nrm); nrm = fmaf(a1.y, a1.y, nrm); nrm = fmaf(a1.z, a1.z, nrm);
    nrm = fmaf(a1.w, a1.w, nrm);
    float dot = x0.x * a0.x;
    dot = fmaf(x0.y, a0.y, dot); dot = fmaf(x0.z, a0.z, dot); dot = fmaf(x0.w, a0.w, dot);
    dot = fmaf(x1.x, a1.x, dot); dot = fmaf(x1.y, a1.y, dot); dot = fmaf(x1.z, a1.z, dot);
    dot = fmaf(x1.w, a1.w, dot);
    float sv = fmaf(-2.f, dot, nrm);
    if (sv < ev || (sv == ev && a < ei)) { ev = sv; ei = a; }
}

__global__ void __launch_bounds__(256)
finalize_kernel(const float* __restrict__ x, const float* __restrict__ anchors,
                const float* __restrict__ sac, const float* __restrict__ somc,
                const int* __restrict__ t, float* __restrict__ out) {
    int q = blockIdx.x * 8 + (threadIdx.x >> 5);
    int lane = threadIdx.x & 31;

    float4 f[SEG]; int bk2[SEG];
    float m1 = FLT_INF;
#pragma unroll
    for (int s = 0; s < SEG; ++s) {
        f[s] = g_f4[s * NQ + q];
        bk2[s] = g_blk2[s * NQ + q];
        m1 = fminf(m1, f[s].x);
    }

    const float4* xp = (const float4*)(x + (size_t)q * DIM);
    float4 x0 = xp[0], x1 = xp[1];
    // coarse-error bound: both operands tf32-rounded => E <= 2^-10 * S
    float S = fabsf(x0.x) * __uint_as_float(g_bmax[0]);
    S = fmaf(fabsf(x0.y), __uint_as_float(g_bmax[1]), S);
    S = fmaf(fabsf(x0.z), __uint_as_float(g_bmax[2]), S);
    S = fmaf(fabsf(x0.w), __uint_as_float(g_bmax[3]), S);
    S = fmaf(fabsf(x1.x), __uint_as_float(g_bmax[4]), S);
    S = fmaf(fabsf(x1.y), __uint_as_float(g_bmax[5]), S);
    S = fmaf(fabsf(x1.z), __uint_as_float(g_bmax[6]), S);
    S = fmaf(fabsf(x1.w), __uint_as_float(g_bmax[7]), S);
    S *= 2.f;
    float thr = m1 + 2.2e-3f * S + 1e-4f * (1.f + S);   // m1 + 2E + slack

    bool fb = false;
#pragma unroll
    for (int s = 0; s < SEG; ++s) fb |= (f[s].z <= thr);   // 3rd-best within window

    float ev = FLT_INF; int ei = 0x7fffffff;
    if (!fb) {
#pragma unroll
        for (int s = 0; s < SEG; ++s) {
            int blk1 = __float_as_int(f[s].w);
            if (f[s].x <= thr) {
                int a0i = s * APS + blk1 * BLKA;
                score_upd(anchors, a0i + lane, x0, x1, ev, ei);
                score_upd(anchors, a0i + 32 + lane, x0, x1, ev, ei);
            }
            if (f[s].y <= thr && bk2[s] != blk1) {
                int a0i = s * APS + bk2[s] * BLKA;
                score_upd(anchors, a0i + lane, x0, x1, ev, ei);
                score_upd(anchors, a0i + 32 + lane, x0, x1, ev, ei);
            }
        }
    } else {
        for (int it = 0; it < MA / 32; ++it)
            score_upd(anchors, it * 32 + lane, x0, x1, ev, ei);
    }
#pragma unroll
    for (int off = 16; off >= 1; off >>= 1) {
        float ov = __shfl_xor_sync(0xffffffffu, ev, off);
        int   oi = __shfl_xor_sync(0xffffffffu, ei, off);
        if (ov < ev || (ov == ev && oi < ei)) { ev = ov; ei = oi; }
    }

    if (lane == 0) {
        int tt = t[q >> 11];                              // N = 2048
        float sa = sac[tt], sb = somc[tt];
        const float4* ap = (const float4*)(anchors + (size_t)ei * DIM);
        float4 a0 = ap[0], a1 = ap[1];
        float4 o0, o1;
        o0.x = sa * x0.x + sb * a0.x; o0.y = sa * x0.y + sb * a0.y;
        o0.z = sa * x0.z + sb * a0.z; o0.w = sa * x0.w + sb * a0.w;
        o1.x = sa * x1.x + sb * a1.x; o1.y = sa * x1.y + sb * a1.y;
        o1.z = sa * x1.z + sb * a1.z; o1.w = sa * x1.w + sb * a1.w;
        float4* op = (float4*)(out + (size_t)q * DIM);
        op[0] = o0; op[1] = o1;
    }
}

// ---------------------------------------------------------------------------
extern "C" void kernel_launch(void* const* d_in, const int* in_sizes, int n_in,
                              void* d_out, int out_size) {
    const float* x    = nullptr;
    const float* anch = nullptr;
    const float* sac  = nullptr;
    const float* somc = nullptr;
    const int*   t    = nullptr;
    for (int i = 0; i < n_in; ++i) {
        int s = in_sizes[i];
        if (s == NQ * DIM && !x)          x    = (const float*)d_in[i];
        else if (s == MA * DIM)           anch = (const float*)d_in[i];
        else if (s == 1000) { if (!sac) sac = (const float*)d_in[i];
                              else      somc = (const float*)d_in[i]; }
        else if (s == 16)                 t    = (const int*)d_in[i];
    }
    coarse_kernel<<<(NQ / 128) * SEG, 128>>>(x, anch);
    finalize_kernel<<<NQ / 8, 256>>>(x, anch, sac, somc, t, (float*)d_out);
}